// round 14
// baseline (speedup 1.0000x reference)
#include <cuda_runtime.h>
#include <cuda_fp16.h>
#include <cstdint>
#include <math.h>

#define NCELL 4096
#define NDRUG 2048
#define DIMF  2040
#define KNN_K 7
#define GAMMA_C 15.0f

static constexpr size_t S_NC = 4096, S_ND = 2048, S_D = 2040;

#define CAP_L 16
#define CAP_C 96
#define CAP_D 160

constexpr size_t OFF_T1C   = 0;
constexpr size_t OFF_SFC   = OFF_T1C  + S_NC * S_D;
constexpr size_t OFF_T1D   = OFF_SFC  + S_NC * S_D;
constexpr size_t OFF_ZA    = OFF_T1D  + S_ND * S_D;
constexpr size_t OFF_ZC    = OFF_ZA   + 2 * S_ND * S_D;
constexpr size_t OFF_EXPSP = OFF_ZC   + S_ND * S_D;
constexpr size_t OFF_DA    = OFF_EXPSP+ S_NC * S_D;
constexpr size_t OFF_CP    = OFF_DA   + 3 * S_ND * S_D;
constexpr size_t OFF_DP    = OFF_CP   + S_NC * S_D;
constexpr size_t OFF_XC    = OFF_DP   + S_ND * S_D;
constexpr size_t OFF_YC    = OFF_XC   + S_NC * S_D;
constexpr size_t OFF_WSC   = OFF_YC   + S_ND * S_D;
constexpr size_t OFF_WSD   = OFF_WSC  + S_D * S_D;
constexpr size_t OFF_WCS   = OFF_WSD  + S_D * S_D;
constexpr size_t OFF_WCC   = OFF_WCS  + S_D * S_D;
constexpr size_t OFF_WDD   = OFF_WCC  + 2 * S_D * S_D;
constexpr size_t OFF_LCV   = OFF_WDD  + 3 * S_D * S_D;
constexpr size_t OFF_LDV   = OFF_LCV + S_NC * CAP_L;
constexpr size_t OFF_DRC   = OFF_LDV + S_ND * CAP_L;
constexpr size_t OFF_DCC   = OFF_DRC + S_NC;
constexpr size_t OFF_DRD   = OFF_DCC + S_NC;
constexpr size_t OFF_DCD   = OFF_DRD + S_ND;
constexpr size_t OFF_LRSC  = OFF_DCD + S_ND;
constexpr size_t OFF_LCSC  = OFF_LRSC + S_NC;
constexpr size_t OFF_LRSD  = OFF_LCSC + S_NC;
constexpr size_t OFF_LCSD  = OFF_LRSD + S_ND;
constexpr size_t OFF_DXA   = OFF_LCSD + S_ND;
constexpr size_t OFF_DYA   = OFF_DXA + S_NC;
constexpr size_t OFF_SELFC = OFF_DYA + S_ND;
constexpr size_t OFF_SELFD = OFF_SELFC + S_NC;
constexpr size_t OFF_RNX   = OFF_SELFD + S_ND;
constexpr size_t OFF_RNY   = OFF_RNX + S_NC;
constexpr size_t OFF_BSC   = OFF_RNY + S_ND;
constexpr size_t OFF_BSD   = OFF_BSC + S_D;
constexpr size_t SCRATCH_TOTAL = OFF_BSD + S_D;

__device__ float g_scratch[SCRATCH_TOTAL];

constexpr size_t I_LAPC_IDX = 0;
constexpr size_t I_LAPD_IDX = I_LAPC_IDX + S_NC * CAP_L;
constexpr size_t I_ADJC_IDX = I_LAPD_IDX + S_ND * CAP_L;
constexpr size_t I_ADJD_IDX = I_ADJC_IDX + S_NC * CAP_C;
constexpr size_t I_LAPC_CNT = I_ADJD_IDX + S_ND * CAP_D;
constexpr size_t I_LAPD_CNT = I_LAPC_CNT + S_NC;
constexpr size_t I_ADJC_CNT = I_LAPD_CNT + S_ND;
constexpr size_t I_ADJD_CNT = I_ADJC_CNT + S_NC;
constexpr size_t ISCRATCH_TOTAL = I_ADJD_CNT + S_ND;

__device__ int g_iscratch[ISCRATCH_TOTAL];

// ---------------- helpers ----------------
__device__ __forceinline__ uint32_t smem_to_u32(const void* p) {
    uint32_t a;
    asm("{ .reg .u64 t; cvta.to.shared.u64 t, %1; cvt.u32.u64 %0, t; }" : "=r"(a) : "l"(p));
    return a;
}

__device__ __forceinline__ uint2 pack4_hi(const float4& x) {
    __half2 h0 = __floats2half2_rn(x.x, x.y);
    __half2 h1 = __floats2half2_rn(x.z, x.w);
    uint2 r;
    r.x = *reinterpret_cast<const uint32_t*>(&h0);
    r.y = *reinterpret_cast<const uint32_t*>(&h1);
    return r;
}

__device__ __forceinline__ void ldmx4(uint32_t* r, uint32_t addr) {
    asm volatile("ldmatrix.sync.aligned.m8n8.x4.shared.b16 {%0,%1,%2,%3}, [%4];"
        : "=r"(r[0]), "=r"(r[1]), "=r"(r[2]), "=r"(r[3]) : "r"(addr));
}

__device__ __forceinline__ void mma16816(float* c, const uint32_t* a, const uint32_t* b) {
    asm volatile(
        "mma.sync.aligned.m16n8k16.row.col.f32.f16.f16.f32 "
        "{%0,%1,%2,%3}, {%4,%5,%6,%7}, {%8,%9}, {%0,%1,%2,%3};"
        : "+f"(c[0]), "+f"(c[1]), "+f"(c[2]), "+f"(c[3])
        : "r"(a[0]), "r"(a[1]), "r"(a[2]), "r"(a[3]), "r"(b[0]), "r"(b[1]));
}

__device__ __forceinline__ void cp_async16(uint32_t sa, const void* ga, int sz) {
    asm volatile("cp.async.cg.shared.global [%0], [%1], 16, %2;"
                 :: "r"(sa), "l"(ga), "r"(sz) : "memory");
}
#define CP_COMMIT() asm volatile("cp.async.commit_group;" ::: "memory")
#define CP_WAIT2()  asm volatile("cp.async.wait_group 2;" ::: "memory")

__device__ __forceinline__ float blockReduceSum(float v) {
    static __shared__ float sh[32];
    __syncthreads();
    int lane = threadIdx.x & 31, w = threadIdx.x >> 5;
    #pragma unroll
    for (int o = 16; o; o >>= 1) v += __shfl_down_sync(0xffffffffu, v, o);
    if (lane == 0) sh[w] = v;
    __syncthreads();
    int nw = (blockDim.x + 31) >> 5;
    v = (threadIdx.x < nw) ? sh[threadIdx.x] : 0.f;
    if (w == 0) {
        #pragma unroll
        for (int o = 16; o; o >>= 1) v += __shfl_down_sync(0xffffffffu, v, o);
    }
    return v;
}

// ---------------- fused kNN threshold + extract ----------------
__device__ __forceinline__ void topk_insert(float* v, float x) {
    if (x <= v[KNN_K - 1]) return;
    v[KNN_K - 1] = x;
    #pragma unroll
    for (int i = KNN_K - 1; i > 0; --i)
        if (v[i] > v[i - 1]) { float t = v[i]; v[i] = v[i - 1]; v[i - 1] = t; }
}

__global__ void knn_extract_kernel(const float* __restrict__ sim, int n,
                                   int* __restrict__ idx, float* __restrict__ val,
                                   int* __restrict__ cnt,
                                   float* __restrict__ drow, float* __restrict__ dcol) {
    extern __shared__ float srow[];
    __shared__ float tk[256 * KNN_K];
    __shared__ int cshared;
    __shared__ float thr_s;
    int r = blockIdx.x, tid = threadIdx.x;
    const float4* p4 = reinterpret_cast<const float4*>(sim + (size_t)r * n);
    int nch = n >> 2;
    for (int j = tid; j < nch; j += 256)
        reinterpret_cast<float4*>(srow)[j] = p4[j];
    if (tid == 0) cshared = 0;
    __syncthreads();
    float v[KNN_K];
    #pragma unroll
    for (int i = 0; i < KNN_K; i++) v[i] = -1e30f;
    for (int j = tid; j < n; j += 256) topk_insert(v, srow[j]);
    #pragma unroll
    for (int i = 0; i < KNN_K; i++) tk[tid * KNN_K + i] = v[i];
    __syncthreads();
    for (int st = 128; st > 0; st >>= 1) {
        if (tid < st) {
            float* a = &tk[tid * KNN_K];
            const float* b = &tk[(tid + st) * KNN_K];
            #pragma unroll
            for (int i = 0; i < KNN_K; i++) v[i] = a[i];
            #pragma unroll
            for (int i = 0; i < KNN_K; i++) topk_insert(v, b[i]);
            #pragma unroll
            for (int i = 0; i < KNN_K; i++) a[i] = v[i];
        }
        __syncthreads();
    }
    if (tid == 0) thr_s = tk[KNN_K - 1];
    __syncthreads();
    float t = thr_s, s = 0.f;
    for (int j = tid; j < n; j += 256) {
        float x = srow[j];
        if (x >= t) {
            int pos = atomicAdd(&cshared, 1);
            if (pos < CAP_L) { idx[(size_t)r * CAP_L + pos] = j; val[(size_t)r * CAP_L + pos] = x; }
            s += x;
            atomicAdd(&dcol[j], x);
        }
    }
    s = blockReduceSum(s);
    if (tid == 0) { drow[r] = s; cnt[r] = min(cshared, CAP_L); }
}

__global__ void extract_adj_kernel(const float* __restrict__ adj,
                                   int* __restrict__ cidx, int* __restrict__ ccnt,
                                   int* __restrict__ didx, int* __restrict__ dcnt) {
    int r = blockIdx.x;
    const float* p = adj + (size_t)r * NDRUG;
    __shared__ int c;
    if (threadIdx.x == 0) c = 0;
    __syncthreads();
    for (int j = threadIdx.x; j < NDRUG; j += blockDim.x) {
        if (p[j] != 0.f) {
            int pos = atomicAdd(&c, 1);
            if (pos < CAP_C) cidx[(size_t)r * CAP_C + pos] = j;
            int dpos = atomicAdd(&dcnt[j], 1);
            if (dpos < CAP_D) didx[(size_t)j * CAP_D + dpos] = r;
        }
    }
    __syncthreads();
    if (threadIdx.x == 0) ccnt[r] = min(c, CAP_C);
}

// laplacian scales only (per-matrix)
__global__ void prep_lap_kernel(const float* __restrict__ dr, const float* __restrict__ dc,
                                int n, float* __restrict__ lrs, float* __restrict__ lcs) {
    int i = blockIdx.x * blockDim.x + threadIdx.x;
    if (i < n) { lrs[i] = rsqrtf(dr[i]); lcs[i] = rsqrtf(dc[i]); }
}

// adjacency scales only
__global__ void prep_adj_kernel(const int* __restrict__ ccnt, const int* __restrict__ dcnt,
                                float* dxa, float* dya, float* selfc, float* selfd) {
    int i = blockIdx.x * blockDim.x + threadIdx.x;
    if (i < NCELL) {
        float r = (float)ccnt[i] + 1.f;
        dxa[i] = rsqrtf(r);
        selfc[i] = 1.f / r + 1.f;
    }
    if (i < NDRUG) {
        float c = (float)dcnt[i] + 1.f;
        dya[i] = rsqrtf(c);
        selfd[i] = 1.f / c + 1.f;
    }
}

// ---------------- SpMM (fp32 source -> fp16 hi-plane out; laplacians) ----------------
__global__ void spmm_kernel(const int* __restrict__ idx, const float* __restrict__ val,
                            const int* __restrict__ cnt, int cap,
                            const float* __restrict__ rscale, const float* __restrict__ cscale,
                            const float* __restrict__ src, int D,
                            __half* __restrict__ out, int OD) {
    int r = blockIdx.x, t = threadIdx.x;
    int n = min(cnt[r], cap);
    int nch = D >> 2;
    const int* ip = idx + (size_t)r * cap;
    const float* vp = val + (size_t)r * cap;
    float4 a0 = make_float4(0.f, 0.f, 0.f, 0.f);
    float4 a1 = make_float4(0.f, 0.f, 0.f, 0.f);
    bool h1 = (t + 256) < nch;
    for (int j = 0; j < n; ++j) {
        int c = ip[j];
        float s = vp[j] * cscale[c];
        const float4* sr = reinterpret_cast<const float4*>(src + (size_t)c * D);
        float4 x = sr[t];
        a0.x = fmaf(s, x.x, a0.x); a0.y = fmaf(s, x.y, a0.y);
        a0.z = fmaf(s, x.z, a0.z); a0.w = fmaf(s, x.w, a0.w);
        if (h1) {
            float4 y = sr[t + 256];
            a1.x = fmaf(s, y.x, a1.x); a1.y = fmaf(s, y.y, a1.y);
            a1.z = fmaf(s, y.z, a1.z); a1.w = fmaf(s, y.w, a1.w);
        }
    }
    float rs = rscale[r];
    a0.x *= rs; a0.y *= rs; a0.z *= rs; a0.w *= rs;
    a1.x *= rs; a1.y *= rs; a1.z *= rs; a1.w *= rs;
    size_t base = (size_t)r * OD + (size_t)t * 4;
    *reinterpret_cast<uint2*>(out + base) = pack4_hi(a0);
    if (h1) *reinterpret_cast<uint2*>(out + base + 1024) = pack4_hi(a1);
}

// ---------------- SpMM (fp16 source, smem indices, unroll 2; accumulate fp32) -------
__global__ void spmm_h_acc_kernel(const int* __restrict__ idx, const int* __restrict__ cnt, int cap,
                                  const float* __restrict__ rscale, const float* __restrict__ cscale,
                                  const __half* __restrict__ src, int Ds,
                                  float* __restrict__ out, int OD) {
    __shared__ int sidx[CAP_D];
    __shared__ float sscale[CAP_D];
    int r = blockIdx.x, t = threadIdx.x;
    int n = min(cnt[r], cap);
    const int* ip = idx + (size_t)r * cap;
    for (int j = t; j < n; j += blockDim.x) {
        int c = ip[j];
        sidx[j] = c;
        sscale[j] = cscale[c];
    }
    __syncthreads();
    int nch = DIMF >> 2;
    float4 a0 = make_float4(0.f, 0.f, 0.f, 0.f);
    float4 a1 = make_float4(0.f, 0.f, 0.f, 0.f);
    bool h1 = (t + 256) < nch;
    int j = 0;
    for (; j + 1 < n; j += 2) {
        int cA = sidx[j], cB = sidx[j + 1];
        float sA = sscale[j], sB = sscale[j + 1];
        const uint2* rA = reinterpret_cast<const uint2*>(src + (size_t)cA * Ds);
        const uint2* rB = reinterpret_cast<const uint2*>(src + (size_t)cB * Ds);
        uint2 xA = rA[t], xB = rB[t];
        uint2 yA, yB;
        if (h1) { yA = rA[t + 256]; yB = rB[t + 256]; }
        float2 a00 = __half22float2(*reinterpret_cast<const __half2*>(&xA.x));
        float2 a01 = __half22float2(*reinterpret_cast<const __half2*>(&xA.y));
        float2 b00 = __half22float2(*reinterpret_cast<const __half2*>(&xB.x));
        float2 b01 = __half22float2(*reinterpret_cast<const __half2*>(&xB.y));
        a0.x = fmaf(sA, a00.x, fmaf(sB, b00.x, a0.x));
        a0.y = fmaf(sA, a00.y, fmaf(sB, b00.y, a0.y));
        a0.z = fmaf(sA, a01.x, fmaf(sB, b01.x, a0.z));
        a0.w = fmaf(sA, a01.y, fmaf(sB, b01.y, a0.w));
        if (h1) {
            float2 a10 = __half22float2(*reinterpret_cast<const __half2*>(&yA.x));
            float2 a11 = __half22float2(*reinterpret_cast<const __half2*>(&yA.y));
            float2 b10 = __half22float2(*reinterpret_cast<const __half2*>(&yB.x));
            float2 b11 = __half22float2(*reinterpret_cast<const __half2*>(&yB.y));
            a1.x = fmaf(sA, a10.x, fmaf(sB, b10.x, a1.x));
            a1.y = fmaf(sA, a10.y, fmaf(sB, b10.y, a1.y));
            a1.z = fmaf(sA, a11.x, fmaf(sB, b11.x, a1.z));
            a1.w = fmaf(sA, a11.y, fmaf(sB, b11.y, a1.w));
        }
    }
    if (j < n) {
        int c = sidx[j];
        float s = sscale[j];
        const uint2* sr = reinterpret_cast<const uint2*>(src + (size_t)c * Ds);
        uint2 x = sr[t];
        float2 x0 = __half22float2(*reinterpret_cast<const __half2*>(&x.x));
        float2 x1 = __half22float2(*reinterpret_cast<const __half2*>(&x.y));
        a0.x = fmaf(s, x0.x, a0.x); a0.y = fmaf(s, x0.y, a0.y);
        a0.z = fmaf(s, x1.x, a0.z); a0.w = fmaf(s, x1.y, a0.w);
        if (h1) {
            uint2 y = sr[t + 256];
            float2 y0 = __half22float2(*reinterpret_cast<const __half2*>(&y.x));
            float2 y1 = __half22float2(*reinterpret_cast<const __half2*>(&y.y));
            a1.x = fmaf(s, y0.x, a1.x); a1.y = fmaf(s, y0.y, a1.y);
            a1.z = fmaf(s, y1.x, a1.z); a1.w = fmaf(s, y1.y, a1.w);
        }
    }
    float rs = rscale[r];
    size_t base = (size_t)r * OD + (size_t)t * 4;
    float4 o = *reinterpret_cast<const float4*>(out + base);
    o.x = fmaf(rs, a0.x, o.x); o.y = fmaf(rs, a0.y, o.y);
    o.z = fmaf(rs, a0.z, o.z); o.w = fmaf(rs, a0.w, o.w);
    *reinterpret_cast<float4*>(out + base) = o;
    if (h1) {
        float4 p = *reinterpret_cast<const float4*>(out + base + 1024);
        p.x = fmaf(rs, a1.x, p.x); p.y = fmaf(rs, a1.y, p.y);
        p.z = fmaf(rs, a1.z, p.z); p.w = fmaf(rs, a1.w, p.w);
        *reinterpret_cast<float4*>(out + base + 1024) = p;
    }
}

// ---------------- dual-source SpMM (fp16 sources share indices; fp16 hi out) --------
__global__ void spmm_h2_kernel(const int* __restrict__ idx, const int* __restrict__ cnt, int cap,
                               const float* __restrict__ rscale, const float* __restrict__ cscale,
                               const __half* __restrict__ srcA, const __half* __restrict__ srcB,
                               int Ds, __half* __restrict__ outA, __half* __restrict__ outB,
                               int OD) {
    __shared__ int sidx[CAP_D];
    __shared__ float sscale[CAP_D];
    int r = blockIdx.x, t = threadIdx.x;
    int n = min(cnt[r], cap);
    const int* ip = idx + (size_t)r * cap;
    for (int j = t; j < n; j += blockDim.x) {
        int c = ip[j];
        sidx[j] = c;
        sscale[j] = cscale[c];
    }
    __syncthreads();
    int nch = DIMF >> 2;
    float4 aA0 = make_float4(0.f, 0.f, 0.f, 0.f), aA1 = aA0;
    float4 aB0 = aA0, aB1 = aA0;
    bool h1 = (t + 256) < nch;
    for (int j = 0; j < n; ++j) {
        int c = sidx[j];
        float s = sscale[j];
        const uint2* rA = reinterpret_cast<const uint2*>(srcA + (size_t)c * Ds);
        const uint2* rB = reinterpret_cast<const uint2*>(srcB + (size_t)c * Ds);
        uint2 xA = rA[t], xB = rB[t];
        uint2 yA, yB;
        if (h1) { yA = rA[t + 256]; yB = rB[t + 256]; }
        float2 p0 = __half22float2(*reinterpret_cast<const __half2*>(&xA.x));
        float2 p1 = __half22float2(*reinterpret_cast<const __half2*>(&xA.y));
        aA0.x = fmaf(s, p0.x, aA0.x); aA0.y = fmaf(s, p0.y, aA0.y);
        aA0.z = fmaf(s, p1.x, aA0.z); aA0.w = fmaf(s, p1.y, aA0.w);
        p0 = __half22float2(*reinterpret_cast<const __half2*>(&xB.x));
        p1 = __half22float2(*reinterpret_cast<const __half2*>(&xB.y));
        aB0.x = fmaf(s, p0.x, aB0.x); aB0.y = fmaf(s, p0.y, aB0.y);
        aB0.z = fmaf(s, p1.x, aB0.z); aB0.w = fmaf(s, p1.y, aB0.w);
        if (h1) {
            p0 = __half22float2(*reinterpret_cast<const __half2*>(&yA.x));
            p1 = __half22float2(*reinterpret_cast<const __half2*>(&yA.y));
            aA1.x = fmaf(s, p0.x, aA1.x); aA1.y = fmaf(s, p0.y, aA1.y);
            aA1.z = fmaf(s, p1.x, aA1.z); aA1.w = fmaf(s, p1.y, aA1.w);
            p0 = __half22float2(*reinterpret_cast<const __half2*>(&yB.x));
            p1 = __half22float2(*reinterpret_cast<const __half2*>(&yB.y));
            aB1.x = fmaf(s, p0.x, aB1.x); aB1.y = fmaf(s, p0.y, aB1.y);
            aB1.z = fmaf(s, p1.x, aB1.z); aB1.w = fmaf(s, p1.y, aB1.w);
        }
    }
    float rs = rscale[r];
    aA0.x *= rs; aA0.y *= rs; aA0.z *= rs; aA0.w *= rs;
    aA1.x *= rs; aA1.y *= rs; aA1.z *= rs; aA1.w *= rs;
    aB0.x *= rs; aB0.y *= rs; aB0.z *= rs; aB0.w *= rs;
    aB1.x *= rs; aB1.y *= rs; aB1.z *= rs; aB1.w *= rs;
    size_t base = (size_t)r * OD + (size_t)t * 4;
    *reinterpret_cast<uint2*>(outA + base) = pack4_hi(aA0);
    *reinterpret_cast<uint2*>(outB + base) = pack4_hi(aB0);
    if (h1) {
        *reinterpret_cast<uint2*>(outA + base + 1024) = pack4_hi(aA1);
        *reinterpret_cast<uint2*>(outB + base + 1024) = pack4_hi(aB1);
    }
}

// ---------------- elementwise ----------------
__global__ void bsum_kernel(const float* b0, const float* b1, const float* b2,
                            const float* c0, const float* c1, const float* c2,
                            float* bsc, float* bsd) {
    int j = blockIdx.x * blockDim.x + threadIdx.x;
    if (j < DIMF) { bsc[j] = b0[j] + b1[j] + b2[j]; bsd[j] = c0[j] + c1[j] + c2[j]; }
}

__global__ void split_row_kernel(const float* __restrict__ src, const float* __restrict__ rscale,
                                 int C, __half* __restrict__ dst, int OD) {
    int r = blockIdx.x;
    const float4* s4 = reinterpret_cast<const float4*>(src + (size_t)r * C);
    float rs = rscale ? rscale[r] : 1.f;
    int nch = C >> 2;
    __half* d = dst + (size_t)r * OD;
    for (int t = threadIdx.x; t < nch; t += blockDim.x) {
        float4 x = s4[t];
        x.x *= rs; x.y *= rs; x.z *= rs; x.w *= rs;
        *reinterpret_cast<uint2*>(d + t * 4) = pack4_hi(x);
    }
}

__global__ void gate_center_kernel(const float* __restrict__ pre, const float* __restrict__ gate,
                                   int cols, __half* __restrict__ xcp, float* __restrict__ rn) {
    extern __shared__ float row[];
    int r = blockIdx.x;
    size_t base = (size_t)r * cols;
    const float4* p4 = reinterpret_cast<const float4*>(pre + base);
    const float4* g4 = reinterpret_cast<const float4*>(gate + base);
    int nch = cols >> 2;
    float s = 0.f;
    for (int t = threadIdx.x; t < nch; t += blockDim.x) {
        float4 p = p4[t], g = g4[t];
        float4 o;
        o.x = fmaxf(p.x * (1.f + g.x), 0.f);
        o.y = fmaxf(p.y * (1.f + g.y), 0.f);
        o.z = fmaxf(p.z * (1.f + g.z), 0.f);
        o.w = fmaxf(p.w * (1.f + g.w), 0.f);
        reinterpret_cast<float4*>(row)[t] = o;
        s += o.x + o.y + o.z + o.w;
    }
    s = blockReduceSum(s);
    __shared__ float mean_s;
    if (threadIdx.x == 0) mean_s = s / (float)cols;
    __syncthreads();
    float mean = mean_s, q = 0.f;
    __half* d = xcp + base;
    for (int t = threadIdx.x; t < nch; t += blockDim.x) {
        float4 o = reinterpret_cast<const float4*>(row)[t];
        o.x -= mean; o.y -= mean; o.z -= mean; o.w -= mean;
        q += o.x * o.x + o.y * o.y + o.z * o.z + o.w * o.w;
        *reinterpret_cast<uint2*>(d + t * 4) = pack4_hi(o);
    }
    q = blockReduceSum(q);
    if (threadIdx.x == 0) rn[r] = rsqrtf(q);
}

// ---------------- mma.sync GEMM: 128x256 tile, plain fp16 1-MMA, 4-stage ----------
#define F_ADD     1
#define F_RELU    2
#define F_PEARSON 4
#define F_PACK1   16

static constexpr int STAGE_BYTES = 49152;
static constexpr int NSTAGE = 4;
static constexpr int TG_SMEM = NSTAGE * STAGE_BYTES;

__device__ __forceinline__ void load_stage(uint32_t st,
    const __half* __restrict__ A, int lda, int bm,
    const __half* __restrict__ B, int ldb, int bn, int N,
    int k0, int K) {
    int tid = threadIdx.x;
    #pragma unroll
    for (int i = 0; i < 4; ++i) {
        int idx = tid + i * 256;
        int r = idx >> 3, c = idx & 7;
        int kc = k0 + c * 8;
        uint32_t sw = (uint32_t)((r * 128 + c * 16) ^ ((r & 7) << 4));
        bool ok = (kc < K);
        const __half* g = A + (size_t)(bm + r) * lda + (ok ? kc : 0);
        cp_async16(st + sw, g, ok ? 16 : 0);
    }
    #pragma unroll
    for (int i = 0; i < 8; ++i) {
        int idx = tid + i * 256;
        int r = idx >> 3, c = idx & 7;
        int kc = k0 + c * 8;
        uint32_t sw = (uint32_t)((r * 128 + c * 16) ^ ((r & 7) << 4));
        int gr = bn + r;
        bool ok = (gr < N) && (kc < K);
        const __half* g = B + (size_t)(ok ? gr : 0) * ldb + (ok ? kc : 0);
        cp_async16(st + 16384 + sw, g, ok ? 16 : 0);
    }
}

__global__ __launch_bounds__(256, 1)
void tgemm_kernel(int M, int N, int K,
                  const __half* __restrict__ A, int lda,
                  const __half* __restrict__ B, int ldb,
                  void* __restrict__ Cv, int ldc,
                  const float* __restrict__ bias, const float* __restrict__ rowscale,
                  const float* __restrict__ rnx, const float* __restrict__ rny, int flags) {
    extern __shared__ char smem[];
    uint32_t sb = smem_to_u32(smem);
    int tid = threadIdx.x, w = tid >> 5, l = tid & 31;
    int bm = blockIdx.y * 128, bn = blockIdx.x * 256;
    int wm = (w >> 2) * 64, wn = (w & 3) * 64;

    float acc[4][8][4];
    #pragma unroll
    for (int i = 0; i < 4; i++)
        #pragma unroll
        for (int j = 0; j < 8; j++)
            #pragma unroll
            for (int q = 0; q < 4; q++) acc[i][j][q] = 0.f;

    const int KT = (K + 63) >> 6;

    #pragma unroll
    for (int s = 0; s < NSTAGE - 1; ++s) {
        if (s < KT)
            load_stage(sb + s * STAGE_BYTES, A, lda, bm, B, ldb, bn, N, s * 64, K);
        CP_COMMIT();
    }

    int lrow = l & 15;
    int lk8  = (l >> 4) * 16;

    for (int kt = 0; kt < KT; ++kt) {
        CP_WAIT2();
        __syncthreads();
        {
            int kn = kt + NSTAGE - 1;
            if (kn < KT)
                load_stage(sb + (uint32_t)(kn % NSTAGE) * STAGE_BYTES,
                           A, lda, bm, B, ldb, bn, N, kn * 64, K);
            CP_COMMIT();
        }
        uint32_t st = sb + (uint32_t)(kt % NSTAGE) * STAGE_BYTES;
        #pragma unroll
        for (int ks = 0; ks < 4; ++ks) {
            int kkb = ks * 32;
            uint32_t ah[4][4], bh[8][2];
            #pragma unroll
            for (int mf = 0; mf < 4; ++mf) {
                int row = wm + mf * 16 + lrow;
                uint32_t sw = (uint32_t)(row * 128 + kkb + lk8) ^ (((uint32_t)(row & 7)) << 4);
                ldmx4(ah[mf], st + sw);
            }
            #pragma unroll
            for (int nh = 0; nh < 4; ++nh) {
                int row = wn + nh * 16 + lrow;
                uint32_t sw = (uint32_t)(row * 128 + kkb + lk8) ^ (((uint32_t)(row & 7)) << 4);
                uint32_t r4[4];
                ldmx4(r4, st + 16384 + sw);
                bh[nh * 2][0] = r4[0]; bh[nh * 2][1] = r4[2];
                bh[nh * 2 + 1][0] = r4[1]; bh[nh * 2 + 1][1] = r4[3];
            }
            #pragma unroll
            for (int mf = 0; mf < 4; ++mf)
                #pragma unroll
                for (int nf = 0; nf < 8; ++nf)
                    mma16816(acc[mf][nf], ah[mf], bh[nf]);
        }
    }

    float* C = (float*)Cv;
    __half* Cb = (__half*)Cv;
    #pragma unroll
    for (int mf = 0; mf < 4; ++mf) {
        int gmb = bm + wm + mf * 16 + (l >> 2);
        #pragma unroll
        for (int hh = 0; hh < 2; ++hh) {
            int gm = gmb + hh * 8;
            float rsv = rowscale ? rowscale[gm] : 1.0f;
            float rx  = (flags & F_PEARSON) ? rnx[gm] : 0.f;
            #pragma unroll
            for (int nf = 0; nf < 8; ++nf) {
                int gn = bn + wn + nf * 8 + 2 * (l & 3);
                if (gn < N) {
                    float v0 = acc[mf][nf][hh * 2 + 0];
                    float v1 = acc[mf][nf][hh * 2 + 1];
                    if (rowscale) { v0 *= rsv; v1 *= rsv; }
                    if (bias) { v0 += bias[gn]; v1 += bias[gn + 1]; }
                    size_t co = (size_t)gm * ldc + gn;
                    if (flags & F_ADD) {
                        float2 c = *reinterpret_cast<const float2*>(C + co);
                        v0 += c.x; v1 += c.y;
                    }
                    if (flags & F_RELU) { v0 = fmaxf(v0, 0.f); v1 = fmaxf(v1, 0.f); }
                    if (flags & F_PEARSON) {
                        v0 = 1.f / (1.f + expf(-GAMMA_C * v0 * rx * rny[gn]));
                        v1 = 1.f / (1.f + expf(-GAMMA_C * v1 * rx * rny[gn + 1]));
                    }
                    if (flags & F_PACK1) {
                        __half2 h = __floats2half2_rn(v0, v1);
                        *reinterpret_cast<uint32_t*>(Cb + co) =
                            *reinterpret_cast<const uint32_t*>(&h);
                    } else {
                        *reinterpret_cast<float2*>(C + co) = make_float2(v0, v1);
                    }
                }
            }
        }
    }
}

// ---------------- host driver ----------------
static inline void launch_tg(int M, int N, int K,
                             const void* A, int lda, const void* B, int ldb,
                             void* C, int ldc,
                             const float* bias, const float* rsc,
                             const float* rnx, const float* rny, int flags, cudaStream_t st) {
    dim3 grid((N + 255) / 256, (M + 127) / 128);
    tgemm_kernel<<<grid, 256, TG_SMEM, st>>>(M, N, K,
        (const __half*)A, lda, (const __half*)B, ldb,
        C, ldc, bias, rsc, rnx, rny, flags);
}

extern "C" void kernel_launch(void* const* d_in, const int* in_sizes, int n_in,
                              void* d_out, int out_size) {
    const float* adj      = (const float*)d_in[0];
    const float* cell_sim = (const float*)d_in[1];
    const float* drug_sim = (const float*)d_in[2];
    const float* expm     = (const float*)d_in[3];
    const float* figm     = (const float*)d_in[4];
    const float* W_sc = (const float*)d_in[5];
    const float* W_sd = (const float*)d_in[6];
    const float* W_cs = (const float*)d_in[7];  const float* b_cs = (const float*)d_in[8];
    const float* W_c1 = (const float*)d_in[9];  const float* b_c1 = (const float*)d_in[10];
    const float* W_c2 = (const float*)d_in[11]; const float* b_c2 = (const float*)d_in[12];
    const float* W_ds = (const float*)d_in[13]; const float* b_ds = (const float*)d_in[14];
    const float* W_d1 = (const float*)d_in[15]; const float* b_d1 = (const float*)d_in[16];
    const float* W_d2 = (const float*)d_in[17]; const float* b_d2 = (const float*)d_in[18];
    float* out = (float*)d_out;

    static cudaStream_t s1 = nullptr, s2 = nullptr;
    static cudaEvent_t eF = nullptr, e0d = nullptr, e1 = nullptr, e2 = nullptr,
                       e4 = nullptr, eP = nullptr, eW = nullptr, eA = nullptr;
    if (!s1) {
        cudaStreamCreateWithFlags(&s1, cudaStreamNonBlocking);
        cudaStreamCreateWithFlags(&s2, cudaStreamNonBlocking);
        cudaEventCreateWithFlags(&eF, cudaEventDisableTiming);
        cudaEventCreateWithFlags(&e0d, cudaEventDisableTiming);
        cudaEventCreateWithFlags(&e1, cudaEventDisableTiming);
        cudaEventCreateWithFlags(&e2, cudaEventDisableTiming);
        cudaEventCreateWithFlags(&e4, cudaEventDisableTiming);
        cudaEventCreateWithFlags(&eP, cudaEventDisableTiming);
        cudaEventCreateWithFlags(&eW, cudaEventDisableTiming);
        cudaEventCreateWithFlags(&eA, cudaEventDisableTiming);
        cudaFuncSetAttribute(tgemm_kernel, cudaFuncAttributeMaxDynamicSharedMemorySize, TG_SMEM);
    }

    float* S = nullptr;
    cudaGetSymbolAddress((void**)&S, g_scratch);
    int* I = nullptr;
    cudaGetSymbolAddress((void**)&I, g_iscratch);

    __half* T1CH = (__half*)(S + OFF_T1C);
    __half* SFCH = (__half*)(S + OFF_SFC);
    __half* T1DH = (__half*)(S + OFF_T1D);
    __half* ZAb = (__half*)(S + OFF_ZA);
    __half* ZCH = (__half*)(S + OFF_ZC);
    __half* EXPSP = (__half*)(S + OFF_EXPSP);
    __half* DAb = (__half*)(S + OFF_DA);
    float* CP  = S + OFF_CP;
    float* DP  = S + OFF_DP;
    __half* XC = (__half*)(S + OFF_XC);
    __half* YC = (__half*)(S + OFF_YC);
    __half* WSCb = (__half*)(S + OFF_WSC);
    __half* WSDb = (__half*)(S + OFF_WSD);
    __half* WCSb = (__half*)(S + OFF_WCS);
    __half* WCCb = (__half*)(S + OFF_WCC);
    __half* WDDb = (__half*)(S + OFF_WDD);
    float* LCV = S + OFF_LCV;   float* LDV = S + OFF_LDV;
    float* DRC = S + OFF_DRC;   float* DCC = S + OFF_DCC;
    float* DRD = S + OFF_DRD;   float* DCD = S + OFF_DCD;
    float* LRSC = S + OFF_LRSC; float* LCSC = S + OFF_LCSC;
    float* LRSD = S + OFF_LRSD; float* LCSD = S + OFF_LCSD;
    float* DXA = S + OFF_DXA;   float* DYA = S + OFF_DYA;
    float* SELFC = S + OFF_SELFC; float* SELFD = S + OFF_SELFD;
    float* RNX = S + OFF_RNX;   float* RNY = S + OFF_RNY;
    float* BSC = S + OFF_BSC;   float* BSD = S + OFF_BSD;

    int* LAPC_IDX = I + I_LAPC_IDX; int* LAPD_IDX = I + I_LAPD_IDX;
    int* ADJC_IDX = I + I_ADJC_IDX; int* ADJD_IDX = I + I_ADJD_IDX;
    int* LAPC_CNT = I + I_LAPC_CNT; int* LAPD_CNT = I + I_LAPD_CNT;
    int* ADJC_CNT = I + I_ADJC_CNT; int* ADJD_CNT = I + I_ADJD_CNT;

    cudaStream_t st = 0;
    const int D = DIMF;

    cudaEventRecord(eF, st);
    cudaStreamWaitEvent(s1, eF, 0);
    cudaStreamWaitEvent(s2, eF, 0);

    // ---- stream 0: cell-critical chain ----
    cudaMemsetAsync(DCC, 0, S_NC * sizeof(float), st);
    knn_extract_kernel<<<NCELL, 256, NCELL * sizeof(float), st>>>(
        cell_sim, NCELL, LAPC_IDX, LCV, LAPC_CNT, DRC, DCC);
    prep_lap_kernel<<<(NCELL + 255) / 256, 256, 0, st>>>(DRC, DCC, NCELL, LRSC, LCSC);
    spmm_kernel<<<NCELL, 256, 0, st>>>(LAPC_IDX, LCV, LAPC_CNT, CAP_L, LRSC, LCSC,
                                       expm, D, T1CH, D);

    // ---- stream 2: drug laplacian chain ----
    cudaMemsetAsync(DCD, 0, S_ND * sizeof(float), s2);
    knn_extract_kernel<<<NDRUG, 256, NDRUG * sizeof(float), s2>>>(
        drug_sim, NDRUG, LAPD_IDX, LDV, LAPD_CNT, DRD, DCD);
    prep_lap_kernel<<<(NDRUG + 255) / 256, 256, 0, s2>>>(DRD, DCD, NDRUG, LRSD, LCSD);
    spmm_kernel<<<NDRUG, 256, 0, s2>>>(LAPD_IDX, LDV, LAPD_CNT, CAP_L, LRSD, LCSD,
                                       figm, D, T1DH, D);
    cudaEventRecord(e0d, s2);

    // ---- stream 1: adjacency + splits ----
    cudaMemsetAsync(ADJD_CNT, 0, S_ND * sizeof(int), s1);
    extract_adj_kernel<<<NCELL, 256, 0, s1>>>(adj, ADJC_IDX, ADJC_CNT, ADJD_IDX, ADJD_CNT);
    prep_adj_kernel<<<(NCELL + 255) / 256, 256, 0, s1>>>(ADJC_CNT, ADJD_CNT,
                                                         DXA, DYA, SELFC, SELFD);
    split_row_kernel<<<DIMF, 256, 0, s1>>>(W_sc, nullptr, D, WSCb, D);
    cudaEventRecord(eW, s1);
    split_row_kernel<<<NCELL, 256, 0, s1>>>(expm, nullptr, D, EXPSP, D);
    cudaEventRecord(eA, s1);
    bsum_kernel<<<(D + 255) / 256, 256, 0, s1>>>(b_cs, b_c1, b_c2, b_ds, b_d1, b_d2, BSC, BSD);
    split_row_kernel<<<NDRUG, 256, 0, s1>>>(figm, nullptr, D, ZAb, 2 * D);
    split_row_kernel<<<NDRUG, 256, 0, s1>>>(figm, SELFD, D, DAb, 3 * D);
    split_row_kernel<<<DIMF, 256, 0, s1>>>(W_sd, nullptr, D, WSDb, D);
    split_row_kernel<<<DIMF, 256, 0, s1>>>(W_cs, nullptr, D, WCSb, D);
    split_row_kernel<<<DIMF, 256, 0, s1>>>(W_c1, nullptr, D, WCCb, 2 * D);
    split_row_kernel<<<DIMF, 256, 0, s1>>>(W_c2, nullptr, D, WCCb + D, 2 * D);
    split_row_kernel<<<DIMF, 256, 0, s1>>>(W_ds, nullptr, D, WDDb, 3 * D);
    split_row_kernel<<<DIMF, 256, 0, s1>>>(W_d1, nullptr, D, WDDb + D, 3 * D);
    split_row_kernel<<<DIMF, 256, 0, s1>>>(W_d2, nullptr, D, WDDb + 2 * D, 3 * D);
    cudaEventRecord(eP, s1);

    // ---- stream 0: SFC -> spmm_h2 -> CP ----
    cudaStreamWaitEvent(st, eW, 0);
    launch_tg(NCELL, D, D, T1CH, D, WSCb, D, SFCH, D,
              0, 0, 0, 0, F_RELU | F_PACK1, st);
    cudaStreamWaitEvent(st, eA, 0);
    spmm_h2_kernel<<<NDRUG, 256, 0, st>>>(ADJD_IDX, ADJD_CNT, CAP_D, DYA, DXA,
                                          EXPSP, SFCH, D,
                                          DAb + D, DAb + 2 * D, 3 * D);
    cudaEventRecord(e2, st);
    cudaStreamWaitEvent(st, eP, 0);
    launch_tg(NCELL, D, D, EXPSP, D, WCSb, D, CP, D,
              BSC, SELFC, 0, 0, 0, st);

    // ---- stream 1: {sfd gemm -> ZC gemm} ----
    cudaStreamWaitEvent(s1, e0d, 0);
    launch_tg(NDRUG, D, D, T1DH, D, WSDb, D,
              (void*)(ZAb + D), 2 * D, 0, 0, 0, 0, F_RELU | F_PACK1, s1);
    launch_tg(NDRUG, D, 2 * D, ZAb, 2 * D, WCCb, 2 * D,
              ZCH, D, 0, 0, 0, 0, F_PACK1, s1);
    cudaEventRecord(e1, s1);

    // ---- stream 0: finish cell side ----
    cudaStreamWaitEvent(st, e1, 0);
    spmm_h_acc_kernel<<<NCELL, 256, 0, st>>>(ADJC_IDX, ADJC_CNT, CAP_C, DXA, DYA,
                                             ZCH, D, CP, D);
    gate_center_kernel<<<NCELL, 256, D * sizeof(float), st>>>(CP, expm, D, XC, RNX);

    // ---- stream 1: DP chain ----
    cudaStreamWaitEvent(s1, e2, 0);
    launch_tg(NDRUG, D, 3 * D, DAb, 3 * D, WDDb, 3 * D,
              DP, D, BSD, 0, 0, 0, 0, s1);
    gate_center_kernel<<<NDRUG, 256, D * sizeof(float), s1>>>(DP, figm, D, YC, RNY);
    cudaEventRecord(e4, s1);

    // ---- decoder ----
    cudaStreamWaitEvent(st, e4, 0);
    launch_tg(NCELL, NDRUG, D, XC, D, YC, D,
              out, NDRUG, 0, 0, RNX, RNY, F_PEARSON, st);
}

// round 15
// speedup vs baseline: 1.0415x; 1.0415x over previous
#include <cuda_runtime.h>
#include <cuda_fp16.h>
#include <cstdint>
#include <math.h>

#define NCELL 4096
#define NDRUG 2048
#define DIMF  2040
#define KNN_K 7
#define GAMMA_C 15.0f

static constexpr size_t S_NC = 4096, S_ND = 2048, S_D = 2040;

#define CAP_L 16
#define CAP_C 96
#define CAP_D 160

constexpr size_t OFF_T1C   = 0;
constexpr size_t OFF_SFC   = OFF_T1C  + S_NC * S_D;
constexpr size_t OFF_T1D   = OFF_SFC  + S_NC * S_D;
constexpr size_t OFF_ZA    = OFF_T1D  + S_ND * S_D;
constexpr size_t OFF_ZC    = OFF_ZA   + 2 * S_ND * S_D;
constexpr size_t OFF_EXPSP = OFF_ZC   + S_ND * S_D;
constexpr size_t OFF_DA    = OFF_EXPSP+ S_NC * S_D;
constexpr size_t OFF_CP    = OFF_DA   + 3 * S_ND * S_D;
constexpr size_t OFF_DP    = OFF_CP   + S_NC * S_D;
constexpr size_t OFF_XC    = OFF_DP   + S_ND * S_D;
constexpr size_t OFF_YC    = OFF_XC   + S_NC * S_D;
constexpr size_t OFF_WSC   = OFF_YC   + S_ND * S_D;
constexpr size_t OFF_WSD   = OFF_WSC  + S_D * S_D;
constexpr size_t OFF_WCS   = OFF_WSD  + S_D * S_D;
constexpr size_t OFF_WCC   = OFF_WCS  + S_D * S_D;
constexpr size_t OFF_WDD   = OFF_WCC  + 2 * S_D * S_D;
constexpr size_t OFF_LCV   = OFF_WDD  + 3 * S_D * S_D;
constexpr size_t OFF_LDV   = OFF_LCV + S_NC * CAP_L;
constexpr size_t OFF_DRC   = OFF_LDV + S_ND * CAP_L;
constexpr size_t OFF_DCC   = OFF_DRC + S_NC;
constexpr size_t OFF_DRD   = OFF_DCC + S_NC;
constexpr size_t OFF_DCD   = OFF_DRD + S_ND;
constexpr size_t OFF_LRSC  = OFF_DCD + S_ND;
constexpr size_t OFF_LCSC  = OFF_LRSC + S_NC;
constexpr size_t OFF_LRSD  = OFF_LCSC + S_NC;
constexpr size_t OFF_LCSD  = OFF_LRSD + S_ND;
constexpr size_t OFF_DXA   = OFF_LCSD + S_ND;
constexpr size_t OFF_DYA   = OFF_DXA + S_NC;
constexpr size_t OFF_SELFC = OFF_DYA + S_ND;
constexpr size_t OFF_SELFD = OFF_SELFC + S_NC;
constexpr size_t OFF_RNX   = OFF_SELFD + S_ND;
constexpr size_t OFF_RNY   = OFF_RNX + S_NC;
constexpr size_t OFF_BSC   = OFF_RNY + S_ND;
constexpr size_t OFF_BSD   = OFF_BSC + S_D;
constexpr size_t SCRATCH_TOTAL = OFF_BSD + S_D;

__device__ float g_scratch[SCRATCH_TOTAL];

constexpr size_t I_LAPC_IDX = 0;
constexpr size_t I_LAPD_IDX = I_LAPC_IDX + S_NC * CAP_L;
constexpr size_t I_ADJC_IDX = I_LAPD_IDX + S_ND * CAP_L;
constexpr size_t I_ADJD_IDX = I_ADJC_IDX + S_NC * CAP_C;
constexpr size_t I_LAPC_CNT = I_ADJD_IDX + S_ND * CAP_D;
constexpr size_t I_LAPD_CNT = I_LAPC_CNT + S_NC;
constexpr size_t I_ADJC_CNT = I_LAPD_CNT + S_ND;
constexpr size_t I_ADJD_CNT = I_ADJC_CNT + S_NC;
constexpr size_t ISCRATCH_TOTAL = I_ADJD_CNT + S_ND;

__device__ int g_iscratch[ISCRATCH_TOTAL];

// ---------------- helpers ----------------
__device__ __forceinline__ uint32_t smem_to_u32(const void* p) {
    uint32_t a;
    asm("{ .reg .u64 t; cvta.to.shared.u64 t, %1; cvt.u32.u64 %0, t; }" : "=r"(a) : "l"(p));
    return a;
}

__device__ __forceinline__ uint2 pack4_hi(const float4& x) {
    __half2 h0 = __floats2half2_rn(x.x, x.y);
    __half2 h1 = __floats2half2_rn(x.z, x.w);
    uint2 r;
    r.x = *reinterpret_cast<const uint32_t*>(&h0);
    r.y = *reinterpret_cast<const uint32_t*>(&h1);
    return r;
}

__device__ __forceinline__ void ldmx4(uint32_t* r, uint32_t addr) {
    asm volatile("ldmatrix.sync.aligned.m8n8.x4.shared.b16 {%0,%1,%2,%3}, [%4];"
        : "=r"(r[0]), "=r"(r[1]), "=r"(r[2]), "=r"(r[3]) : "r"(addr));
}

__device__ __forceinline__ void mma16816(float* c, const uint32_t* a, const uint32_t* b) {
    asm volatile(
        "mma.sync.aligned.m16n8k16.row.col.f32.f16.f16.f32 "
        "{%0,%1,%2,%3}, {%4,%5,%6,%7}, {%8,%9}, {%0,%1,%2,%3};"
        : "+f"(c[0]), "+f"(c[1]), "+f"(c[2]), "+f"(c[3])
        : "r"(a[0]), "r"(a[1]), "r"(a[2]), "r"(a[3]), "r"(b[0]), "r"(b[1]));
}

__device__ __forceinline__ void cp_async16(uint32_t sa, const void* ga, int sz) {
    asm volatile("cp.async.cg.shared.global [%0], [%1], 16, %2;"
                 :: "r"(sa), "l"(ga), "r"(sz) : "memory");
}
#define CP_COMMIT() asm volatile("cp.async.commit_group;" ::: "memory")
#define CP_WAIT2()  asm volatile("cp.async.wait_group 2;" ::: "memory")

__device__ __forceinline__ float blockReduceSum(float v) {
    static __shared__ float sh[32];
    __syncthreads();
    int lane = threadIdx.x & 31, w = threadIdx.x >> 5;
    #pragma unroll
    for (int o = 16; o; o >>= 1) v += __shfl_down_sync(0xffffffffu, v, o);
    if (lane == 0) sh[w] = v;
    __syncthreads();
    int nw = (blockDim.x + 31) >> 5;
    v = (threadIdx.x < nw) ? sh[threadIdx.x] : 0.f;
    if (w == 0) {
        #pragma unroll
        for (int o = 16; o; o >>= 1) v += __shfl_down_sync(0xffffffffu, v, o);
    }
    return v;
}

// ---------------- fused kNN threshold + extract ----------------
__device__ __forceinline__ void topk_insert(float* v, float x) {
    if (x <= v[KNN_K - 1]) return;
    v[KNN_K - 1] = x;
    #pragma unroll
    for (int i = KNN_K - 1; i > 0; --i)
        if (v[i] > v[i - 1]) { float t = v[i]; v[i] = v[i - 1]; v[i - 1] = t; }
}

__global__ void knn_extract_kernel(const float* __restrict__ sim, int n,
                                   int* __restrict__ idx, float* __restrict__ val,
                                   int* __restrict__ cnt,
                                   float* __restrict__ drow, float* __restrict__ dcol) {
    extern __shared__ float srow[];
    __shared__ float tk[256 * KNN_K];
    __shared__ int cshared;
    __shared__ float thr_s;
    int r = blockIdx.x, tid = threadIdx.x;
    const float4* p4 = reinterpret_cast<const float4*>(sim + (size_t)r * n);
    int nch = n >> 2;
    for (int j = tid; j < nch; j += 256)
        reinterpret_cast<float4*>(srow)[j] = p4[j];
    if (tid == 0) cshared = 0;
    __syncthreads();
    float v[KNN_K];
    #pragma unroll
    for (int i = 0; i < KNN_K; i++) v[i] = -1e30f;
    for (int j = tid; j < n; j += 256) topk_insert(v, srow[j]);
    #pragma unroll
    for (int i = 0; i < KNN_K; i++) tk[tid * KNN_K + i] = v[i];
    __syncthreads();
    for (int st = 128; st > 0; st >>= 1) {
        if (tid < st) {
            float* a = &tk[tid * KNN_K];
            const float* b = &tk[(tid + st) * KNN_K];
            #pragma unroll
            for (int i = 0; i < KNN_K; i++) v[i] = a[i];
            #pragma unroll
            for (int i = 0; i < KNN_K; i++) topk_insert(v, b[i]);
            #pragma unroll
            for (int i = 0; i < KNN_K; i++) a[i] = v[i];
        }
        __syncthreads();
    }
    if (tid == 0) thr_s = tk[KNN_K - 1];
    __syncthreads();
    float t = thr_s, s = 0.f;
    for (int j = tid; j < n; j += 256) {
        float x = srow[j];
        if (x >= t) {
            int pos = atomicAdd(&cshared, 1);
            if (pos < CAP_L) { idx[(size_t)r * CAP_L + pos] = j; val[(size_t)r * CAP_L + pos] = x; }
            s += x;
            atomicAdd(&dcol[j], x);
        }
    }
    s = blockReduceSum(s);
    if (tid == 0) { drow[r] = s; cnt[r] = min(cshared, CAP_L); }
}

__global__ void extract_adj_kernel(const float* __restrict__ adj,
                                   int* __restrict__ cidx, int* __restrict__ ccnt,
                                   int* __restrict__ didx, int* __restrict__ dcnt) {
    int r = blockIdx.x;
    const float* p = adj + (size_t)r * NDRUG;
    __shared__ int c;
    if (threadIdx.x == 0) c = 0;
    __syncthreads();
    for (int j = threadIdx.x; j < NDRUG; j += blockDim.x) {
        if (p[j] != 0.f) {
            int pos = atomicAdd(&c, 1);
            if (pos < CAP_C) cidx[(size_t)r * CAP_C + pos] = j;
            int dpos = atomicAdd(&dcnt[j], 1);
            if (dpos < CAP_D) didx[(size_t)j * CAP_D + dpos] = r;
        }
    }
    __syncthreads();
    if (threadIdx.x == 0) ccnt[r] = min(c, CAP_C);
}

__global__ void prep_scales_kernel(const float* drc, const float* dcc,
                                   const float* drd, const float* dcd,
                                   const int* ccnt, const int* dcnt,
                                   float* lrsc, float* lcsc, float* lrsd, float* lcsd,
                                   float* dxa, float* dya, float* selfc, float* selfd) {
    int i = blockIdx.x * blockDim.x + threadIdx.x;
    if (i < NCELL) {
        lrsc[i] = rsqrtf(drc[i]);
        lcsc[i] = rsqrtf(dcc[i]);
        float r = (float)ccnt[i] + 1.f;
        dxa[i] = rsqrtf(r);
        selfc[i] = 1.f / r + 1.f;
    }
    if (i < NDRUG) {
        lrsd[i] = rsqrtf(drd[i]);
        lcsd[i] = rsqrtf(dcd[i]);
        float c = (float)dcnt[i] + 1.f;
        dya[i] = rsqrtf(c);
        selfd[i] = 1.f / c + 1.f;
    }
}

// ---------------- SpMM (fp32 source -> fp16 hi-plane out; laplacians) ----------------
__global__ void spmm_kernel(const int* __restrict__ idx, const float* __restrict__ val,
                            const int* __restrict__ cnt, int cap,
                            const float* __restrict__ rscale, const float* __restrict__ cscale,
                            const float* __restrict__ src, int D,
                            __half* __restrict__ out, int OD) {
    int r = blockIdx.x, t = threadIdx.x;
    int n = min(cnt[r], cap);
    int nch = D >> 2;
    const int* ip = idx + (size_t)r * cap;
    const float* vp = val + (size_t)r * cap;
    float4 a0 = make_float4(0.f, 0.f, 0.f, 0.f);
    float4 a1 = make_float4(0.f, 0.f, 0.f, 0.f);
    bool h1 = (t + 256) < nch;
    for (int j = 0; j < n; ++j) {
        int c = ip[j];
        float s = vp[j] * cscale[c];
        const float4* sr = reinterpret_cast<const float4*>(src + (size_t)c * D);
        float4 x = sr[t];
        a0.x = fmaf(s, x.x, a0.x); a0.y = fmaf(s, x.y, a0.y);
        a0.z = fmaf(s, x.z, a0.z); a0.w = fmaf(s, x.w, a0.w);
        if (h1) {
            float4 y = sr[t + 256];
            a1.x = fmaf(s, y.x, a1.x); a1.y = fmaf(s, y.y, a1.y);
            a1.z = fmaf(s, y.z, a1.z); a1.w = fmaf(s, y.w, a1.w);
        }
    }
    float rs = rscale[r];
    a0.x *= rs; a0.y *= rs; a0.z *= rs; a0.w *= rs;
    a1.x *= rs; a1.y *= rs; a1.z *= rs; a1.w *= rs;
    size_t base = (size_t)r * OD + (size_t)t * 4;
    *reinterpret_cast<uint2*>(out + base) = pack4_hi(a0);
    if (h1) *reinterpret_cast<uint2*>(out + base + 1024) = pack4_hi(a1);
}

// ---------------- fused SpMM(fp16 gather) + add CP + gate + center (cell side) -------
__global__ void spmm_gate_kernel(const int* __restrict__ idx, const int* __restrict__ cnt, int cap,
                                 const float* __restrict__ rscale, const float* __restrict__ cscale,
                                 const __half* __restrict__ src, int Ds,
                                 const float* __restrict__ CP, const float* __restrict__ gate,
                                 int cols, __half* __restrict__ xcp, float* __restrict__ rn) {
    extern __shared__ float row[];
    __shared__ int sidx[CAP_C];
    __shared__ float sscale[CAP_C];
    int r = blockIdx.x, t = threadIdx.x;
    int n = min(cnt[r], cap);
    const int* ip = idx + (size_t)r * cap;
    for (int j = t; j < n; j += blockDim.x) {
        int c = ip[j];
        sidx[j] = c;
        sscale[j] = cscale[c];
    }
    __syncthreads();
    int nch = cols >> 2;                 // 510
    float4 a0 = make_float4(0.f, 0.f, 0.f, 0.f);
    float4 a1 = make_float4(0.f, 0.f, 0.f, 0.f);
    bool h1 = (t + 256) < nch;
    int j = 0;
    for (; j + 1 < n; j += 2) {
        int cA = sidx[j], cB = sidx[j + 1];
        float sA = sscale[j], sB = sscale[j + 1];
        const uint2* rA = reinterpret_cast<const uint2*>(src + (size_t)cA * Ds);
        const uint2* rB = reinterpret_cast<const uint2*>(src + (size_t)cB * Ds);
        uint2 xA = rA[t], xB = rB[t];
        uint2 yA, yB;
        if (h1) { yA = rA[t + 256]; yB = rB[t + 256]; }
        float2 a00 = __half22float2(*reinterpret_cast<const __half2*>(&xA.x));
        float2 a01 = __half22float2(*reinterpret_cast<const __half2*>(&xA.y));
        float2 b00 = __half22float2(*reinterpret_cast<const __half2*>(&xB.x));
        float2 b01 = __half22float2(*reinterpret_cast<const __half2*>(&xB.y));
        a0.x = fmaf(sA, a00.x, fmaf(sB, b00.x, a0.x));
        a0.y = fmaf(sA, a00.y, fmaf(sB, b00.y, a0.y));
        a0.z = fmaf(sA, a01.x, fmaf(sB, b01.x, a0.z));
        a0.w = fmaf(sA, a01.y, fmaf(sB, b01.y, a0.w));
        if (h1) {
            float2 a10 = __half22float2(*reinterpret_cast<const __half2*>(&yA.x));
            float2 a11 = __half22float2(*reinterpret_cast<const __half2*>(&yA.y));
            float2 b10 = __half22float2(*reinterpret_cast<const __half2*>(&yB.x));
            float2 b11 = __half22float2(*reinterpret_cast<const __half2*>(&yB.y));
            a1.x = fmaf(sA, a10.x, fmaf(sB, b10.x, a1.x));
            a1.y = fmaf(sA, a10.y, fmaf(sB, b10.y, a1.y));
            a1.z = fmaf(sA, a11.x, fmaf(sB, b11.x, a1.z));
            a1.w = fmaf(sA, a11.y, fmaf(sB, b11.y, a1.w));
        }
    }
    if (j < n) {
        int c = sidx[j];
        float s = sscale[j];
        const uint2* sr = reinterpret_cast<const uint2*>(src + (size_t)c * Ds);
        uint2 x = sr[t];
        float2 x0 = __half22float2(*reinterpret_cast<const __half2*>(&x.x));
        float2 x1 = __half22float2(*reinterpret_cast<const __half2*>(&x.y));
        a0.x = fmaf(s, x0.x, a0.x); a0.y = fmaf(s, x0.y, a0.y);
        a0.z = fmaf(s, x1.x, a0.z); a0.w = fmaf(s, x1.y, a0.w);
        if (h1) {
            uint2 y = sr[t + 256];
            float2 y0 = __half22float2(*reinterpret_cast<const __half2*>(&y.x));
            float2 y1 = __half22float2(*reinterpret_cast<const __half2*>(&y.y));
            a1.x = fmaf(s, y0.x, a1.x); a1.y = fmaf(s, y0.y, a1.y);
            a1.z = fmaf(s, y1.x, a1.z); a1.w = fmaf(s, y1.y, a1.w);
        }
    }
    float rs = rscale[r];
    size_t base = (size_t)r * cols;
    const float4* cp4 = reinterpret_cast<const float4*>(CP + base);
    const float4* g4  = reinterpret_cast<const float4*>(gate + base);
    float ssum = 0.f;
    {
        float4 cp = cp4[t], g = g4[t];
        float4 o;
        o.x = fmaxf(fmaf(rs, a0.x, cp.x) * (1.f + g.x), 0.f);
        o.y = fmaxf(fmaf(rs, a0.y, cp.y) * (1.f + g.y), 0.f);
        o.z = fmaxf(fmaf(rs, a0.z, cp.z) * (1.f + g.z), 0.f);
        o.w = fmaxf(fmaf(rs, a0.w, cp.w) * (1.f + g.w), 0.f);
        reinterpret_cast<float4*>(row)[t] = o;
        ssum += o.x + o.y + o.z + o.w;
    }
    if (h1) {
        float4 cp = cp4[t + 256], g = g4[t + 256];
        float4 o;
        o.x = fmaxf(fmaf(rs, a1.x, cp.x) * (1.f + g.x), 0.f);
        o.y = fmaxf(fmaf(rs, a1.y, cp.y) * (1.f + g.y), 0.f);
        o.z = fmaxf(fmaf(rs, a1.z, cp.z) * (1.f + g.z), 0.f);
        o.w = fmaxf(fmaf(rs, a1.w, cp.w) * (1.f + g.w), 0.f);
        reinterpret_cast<float4*>(row)[t + 256] = o;
        ssum += o.x + o.y + o.z + o.w;
    }
    ssum = blockReduceSum(ssum);
    __shared__ float mean_s;
    if (t == 0) mean_s = ssum / (float)cols;
    __syncthreads();
    float mean = mean_s, q = 0.f;
    __half* d = xcp + base;
    for (int tt = t; tt < nch; tt += blockDim.x) {
        float4 o = reinterpret_cast<const float4*>(row)[tt];
        o.x -= mean; o.y -= mean; o.z -= mean; o.w -= mean;
        q += o.x * o.x + o.y * o.y + o.z * o.z + o.w * o.w;
        *reinterpret_cast<uint2*>(d + tt * 4) = pack4_hi(o);
    }
    q = blockReduceSum(q);
    if (t == 0) rn[r] = rsqrtf(q);
}

// ---------------- dual-source SpMM (fp16 sources share indices; fp16 hi out) --------
__global__ void spmm_h2_kernel(const int* __restrict__ idx, const int* __restrict__ cnt, int cap,
                               const float* __restrict__ rscale, const float* __restrict__ cscale,
                               const __half* __restrict__ srcA, const __half* __restrict__ srcB,
                               int Ds, __half* __restrict__ outA, __half* __restrict__ outB,
                               int OD) {
    __shared__ int sidx[CAP_D];
    __shared__ float sscale[CAP_D];
    int r = blockIdx.x, t = threadIdx.x;
    int n = min(cnt[r], cap);
    const int* ip = idx + (size_t)r * cap;
    for (int j = t; j < n; j += blockDim.x) {
        int c = ip[j];
        sidx[j] = c;
        sscale[j] = cscale[c];
    }
    __syncthreads();
    int nch = DIMF >> 2;
    float4 aA0 = make_float4(0.f, 0.f, 0.f, 0.f), aA1 = aA0;
    float4 aB0 = aA0, aB1 = aA0;
    bool h1 = (t + 256) < nch;
    for (int j = 0; j < n; ++j) {
        int c = sidx[j];
        float s = sscale[j];
        const uint2* rA = reinterpret_cast<const uint2*>(srcA + (size_t)c * Ds);
        const uint2* rB = reinterpret_cast<const uint2*>(srcB + (size_t)c * Ds);
        uint2 xA = rA[t], xB = rB[t];
        uint2 yA, yB;
        if (h1) { yA = rA[t + 256]; yB = rB[t + 256]; }
        float2 p0 = __half22float2(*reinterpret_cast<const __half2*>(&xA.x));
        float2 p1 = __half22float2(*reinterpret_cast<const __half2*>(&xA.y));
        aA0.x = fmaf(s, p0.x, aA0.x); aA0.y = fmaf(s, p0.y, aA0.y);
        aA0.z = fmaf(s, p1.x, aA0.z); aA0.w = fmaf(s, p1.y, aA0.w);
        p0 = __half22float2(*reinterpret_cast<const __half2*>(&xB.x));
        p1 = __half22float2(*reinterpret_cast<const __half2*>(&xB.y));
        aB0.x = fmaf(s, p0.x, aB0.x); aB0.y = fmaf(s, p0.y, aB0.y);
        aB0.z = fmaf(s, p1.x, aB0.z); aB0.w = fmaf(s, p1.y, aB0.w);
        if (h1) {
            p0 = __half22float2(*reinterpret_cast<const __half2*>(&yA.x));
            p1 = __half22float2(*reinterpret_cast<const __half2*>(&yA.y));
            aA1.x = fmaf(s, p0.x, aA1.x); aA1.y = fmaf(s, p0.y, aA1.y);
            aA1.z = fmaf(s, p1.x, aA1.z); aA1.w = fmaf(s, p1.y, aA1.w);
            p0 = __half22float2(*reinterpret_cast<const __half2*>(&yB.x));
            p1 = __half22float2(*reinterpret_cast<const __half2*>(&yB.y));
            aB1.x = fmaf(s, p0.x, aB1.x); aB1.y = fmaf(s, p0.y, aB1.y);
            aB1.z = fmaf(s, p1.x, aB1.z); aB1.w = fmaf(s, p1.y, aB1.w);
        }
    }
    float rs = rscale[r];
    aA0.x *= rs; aA0.y *= rs; aA0.z *= rs; aA0.w *= rs;
    aA1.x *= rs; aA1.y *= rs; aA1.z *= rs; aA1.w *= rs;
    aB0.x *= rs; aB0.y *= rs; aB0.z *= rs; aB0.w *= rs;
    aB1.x *= rs; aB1.y *= rs; aB1.z *= rs; aB1.w *= rs;
    size_t base = (size_t)r * OD + (size_t)t * 4;
    *reinterpret_cast<uint2*>(outA + base) = pack4_hi(aA0);
    *reinterpret_cast<uint2*>(outB + base) = pack4_hi(aB0);
    if (h1) {
        *reinterpret_cast<uint2*>(outA + base + 1024) = pack4_hi(aA1);
        *reinterpret_cast<uint2*>(outB + base + 1024) = pack4_hi(aB1);
    }
}

// ---------------- elementwise ----------------
__global__ void bsum_kernel(const float* b0, const float* b1, const float* b2,
                            const float* c0, const float* c1, const float* c2,
                            float* bsc, float* bsd) {
    int j = blockIdx.x * blockDim.x + threadIdx.x;
    if (j < DIMF) { bsc[j] = b0[j] + b1[j] + b2[j]; bsd[j] = c0[j] + c1[j] + c2[j]; }
}

__global__ void split_row_kernel(const float* __restrict__ src, const float* __restrict__ rscale,
                                 int C, __half* __restrict__ dst, int OD) {
    int r = blockIdx.x;
    const float4* s4 = reinterpret_cast<const float4*>(src + (size_t)r * C);
    float rs = rscale ? rscale[r] : 1.f;
    int nch = C >> 2;
    __half* d = dst + (size_t)r * OD;
    for (int t = threadIdx.x; t < nch; t += blockDim.x) {
        float4 x = s4[t];
        x.x *= rs; x.y *= rs; x.z *= rs; x.w *= rs;
        *reinterpret_cast<uint2*>(d + t * 4) = pack4_hi(x);
    }
}

__global__ void gate_center_kernel(const float* __restrict__ pre, const float* __restrict__ gate,
                                   int cols, __half* __restrict__ xcp, float* __restrict__ rn) {
    extern __shared__ float row[];
    int r = blockIdx.x;
    size_t base = (size_t)r * cols;
    const float4* p4 = reinterpret_cast<const float4*>(pre + base);
    const float4* g4 = reinterpret_cast<const float4*>(gate + base);
    int nch = cols >> 2;
    float s = 0.f;
    for (int t = threadIdx.x; t < nch; t += blockDim.x) {
        float4 p = p4[t], g = g4[t];
        float4 o;
        o.x = fmaxf(p.x * (1.f + g.x), 0.f);
        o.y = fmaxf(p.y * (1.f + g.y), 0.f);
        o.z = fmaxf(p.z * (1.f + g.z), 0.f);
        o.w = fmaxf(p.w * (1.f + g.w), 0.f);
        reinterpret_cast<float4*>(row)[t] = o;
        s += o.x + o.y + o.z + o.w;
    }
    s = blockReduceSum(s);
    __shared__ float mean_s;
    if (threadIdx.x == 0) mean_s = s / (float)cols;
    __syncthreads();
    float mean = mean_s, q = 0.f;
    __half* d = xcp + base;
    for (int t = threadIdx.x; t < nch; t += blockDim.x) {
        float4 o = reinterpret_cast<const float4*>(row)[t];
        o.x -= mean; o.y -= mean; o.z -= mean; o.w -= mean;
        q += o.x * o.x + o.y * o.y + o.z * o.z + o.w * o.w;
        *reinterpret_cast<uint2*>(d + t * 4) = pack4_hi(o);
    }
    q = blockReduceSum(q);
    if (threadIdx.x == 0) rn[r] = rsqrtf(q);
}

// ---------------- mma.sync GEMM: 128x256 tile, plain fp16 1-MMA, 4-stage ----------
#define F_ADD     1
#define F_RELU    2
#define F_PEARSON 4
#define F_PACK1   16

static constexpr int STAGE_BYTES = 49152;
static constexpr int NSTAGE = 4;
static constexpr int TG_SMEM = NSTAGE * STAGE_BYTES;

__device__ __forceinline__ void load_stage(uint32_t st,
    const __half* __restrict__ A, int lda, int bm,
    const __half* __restrict__ B, int ldb, int bn, int N,
    int k0, int K) {
    int tid = threadIdx.x;
    #pragma unroll
    for (int i = 0; i < 4; ++i) {
        int idx = tid + i * 256;
        int r = idx >> 3, c = idx & 7;
        int kc = k0 + c * 8;
        uint32_t sw = (uint32_t)((r * 128 + c * 16) ^ ((r & 7) << 4));
        bool ok = (kc < K);
        const __half* g = A + (size_t)(bm + r) * lda + (ok ? kc : 0);
        cp_async16(st + sw, g, ok ? 16 : 0);
    }
    #pragma unroll
    for (int i = 0; i < 8; ++i) {
        int idx = tid + i * 256;
        int r = idx >> 3, c = idx & 7;
        int kc = k0 + c * 8;
        uint32_t sw = (uint32_t)((r * 128 + c * 16) ^ ((r & 7) << 4));
        int gr = bn + r;
        bool ok = (gr < N) && (kc < K);
        const __half* g = B + (size_t)(ok ? gr : 0) * ldb + (ok ? kc : 0);
        cp_async16(st + 16384 + sw, g, ok ? 16 : 0);
    }
}

__global__ __launch_bounds__(256, 1)
void tgemm_kernel(int M, int N, int K,
                  const __half* __restrict__ A, int lda,
                  const __half* __restrict__ B, int ldb,
                  void* __restrict__ Cv, int ldc,
                  const float* __restrict__ bias, const float* __restrict__ rowscale,
                  const float* __restrict__ rnx, const float* __restrict__ rny, int flags) {
    extern __shared__ char smem[];
    uint32_t sb = smem_to_u32(smem);
    int tid = threadIdx.x, w = tid >> 5, l = tid & 31;
    int bm = blockIdx.y * 128, bn = blockIdx.x * 256;
    int wm = (w >> 2) * 64, wn = (w & 3) * 64;

    float acc[4][8][4];
    #pragma unroll
    for (int i = 0; i < 4; i++)
        #pragma unroll
        for (int j = 0; j < 8; j++)
            #pragma unroll
            for (int q = 0; q < 4; q++) acc[i][j][q] = 0.f;

    const int KT = (K + 63) >> 6;

    #pragma unroll
    for (int s = 0; s < NSTAGE - 1; ++s) {
        if (s < KT)
            load_stage(sb + s * STAGE_BYTES, A, lda, bm, B, ldb, bn, N, s * 64, K);
        CP_COMMIT();
    }

    int lrow = l & 15;
    int lk8  = (l >> 4) * 16;

    for (int kt = 0; kt < KT; ++kt) {
        CP_WAIT2();
        __syncthreads();
        {
            int kn = kt + NSTAGE - 1;
            if (kn < KT)
                load_stage(sb + (uint32_t)(kn % NSTAGE) * STAGE_BYTES,
                           A, lda, bm, B, ldb, bn, N, kn * 64, K);
            CP_COMMIT();
        }
        uint32_t st = sb + (uint32_t)(kt % NSTAGE) * STAGE_BYTES;
        #pragma unroll
        for (int ks = 0; ks < 4; ++ks) {
            int kkb = ks * 32;
            uint32_t ah[4][4], bh[8][2];
            #pragma unroll
            for (int mf = 0; mf < 4; ++mf) {
                int row = wm + mf * 16 + lrow;
                uint32_t sw = (uint32_t)(row * 128 + kkb + lk8) ^ (((uint32_t)(row & 7)) << 4);
                ldmx4(ah[mf], st + sw);
            }
            #pragma unroll
            for (int nh = 0; nh < 4; ++nh) {
                int row = wn + nh * 16 + lrow;
                uint32_t sw = (uint32_t)(row * 128 + kkb + lk8) ^ (((uint32_t)(row & 7)) << 4);
                uint32_t r4[4];
                ldmx4(r4, st + 16384 + sw);
                bh[nh * 2][0] = r4[0]; bh[nh * 2][1] = r4[2];
                bh[nh * 2 + 1][0] = r4[1]; bh[nh * 2 + 1][1] = r4[3];
            }
            #pragma unroll
            for (int mf = 0; mf < 4; ++mf)
                #pragma unroll
                for (int nf = 0; nf < 8; ++nf)
                    mma16816(acc[mf][nf], ah[mf], bh[nf]);
        }
    }

    float* C = (float*)Cv;
    __half* Cb = (__half*)Cv;
    #pragma unroll
    for (int mf = 0; mf < 4; ++mf) {
        int gmb = bm + wm + mf * 16 + (l >> 2);
        #pragma unroll
        for (int hh = 0; hh < 2; ++hh) {
            int gm = gmb + hh * 8;
            float rsv = rowscale ? rowscale[gm] : 1.0f;
            float rx  = (flags & F_PEARSON) ? rnx[gm] : 0.f;
            #pragma unroll
            for (int nf = 0; nf < 8; ++nf) {
                int gn = bn + wn + nf * 8 + 2 * (l & 3);
                if (gn < N) {
                    float v0 = acc[mf][nf][hh * 2 + 0];
                    float v1 = acc[mf][nf][hh * 2 + 1];
                    if (rowscale) { v0 *= rsv; v1 *= rsv; }
                    if (bias) { v0 += bias[gn]; v1 += bias[gn + 1]; }
                    size_t co = (size_t)gm * ldc + gn;
                    if (flags & F_ADD) {
                        float2 c = *reinterpret_cast<const float2*>(C + co);
                        v0 += c.x; v1 += c.y;
                    }
                    if (flags & F_RELU) { v0 = fmaxf(v0, 0.f); v1 = fmaxf(v1, 0.f); }
                    if (flags & F_PEARSON) {
                        v0 = 1.f / (1.f + expf(-GAMMA_C * v0 * rx * rny[gn]));
                        v1 = 1.f / (1.f + expf(-GAMMA_C * v1 * rx * rny[gn + 1]));
                    }
                    if (flags & F_PACK1) {
                        __half2 h = __floats2half2_rn(v0, v1);
                        *reinterpret_cast<uint32_t*>(Cb + co) =
                            *reinterpret_cast<const uint32_t*>(&h);
                    } else {
                        *reinterpret_cast<float2*>(C + co) = make_float2(v0, v1);
                    }
                }
            }
        }
    }
}

// ---------------- host driver ----------------
static inline void launch_tg(int M, int N, int K,
                             const void* A, int lda, const void* B, int ldb,
                             void* C, int ldc,
                             const float* bias, const float* rsc,
                             const float* rnx, const float* rny, int flags, cudaStream_t st) {
    dim3 grid((N + 255) / 256, (M + 127) / 128);
    tgemm_kernel<<<grid, 256, TG_SMEM, st>>>(M, N, K,
        (const __half*)A, lda, (const __half*)B, ldb,
        C, ldc, bias, rsc, rnx, rny, flags);
}

extern "C" void kernel_launch(void* const* d_in, const int* in_sizes, int n_in,
                              void* d_out, int out_size) {
    const float* adj      = (const float*)d_in[0];
    const float* cell_sim = (const float*)d_in[1];
    const float* drug_sim = (const float*)d_in[2];
    const float* expm     = (const float*)d_in[3];
    const float* figm     = (const float*)d_in[4];
    const float* W_sc = (const float*)d_in[5];
    const float* W_sd = (const float*)d_in[6];
    const float* W_cs = (const float*)d_in[7];  const float* b_cs = (const float*)d_in[8];
    const float* W_c1 = (const float*)d_in[9];  const float* b_c1 = (const float*)d_in[10];
    const float* W_c2 = (const float*)d_in[11]; const float* b_c2 = (const float*)d_in[12];
    const float* W_ds = (const float*)d_in[13]; const float* b_ds = (const float*)d_in[14];
    const float* W_d1 = (const float*)d_in[15]; const float* b_d1 = (const float*)d_in[16];
    const float* W_d2 = (const float*)d_in[17]; const float* b_d2 = (const float*)d_in[18];
    float* out = (float*)d_out;

    static cudaStream_t s1 = nullptr;
    static cudaEvent_t eF = nullptr, e0 = nullptr, e1 = nullptr, e2 = nullptr,
                       e4 = nullptr, eP = nullptr;
    if (!s1) {
        cudaStreamCreateWithFlags(&s1, cudaStreamNonBlocking);
        cudaEventCreateWithFlags(&eF, cudaEventDisableTiming);
        cudaEventCreateWithFlags(&e0, cudaEventDisableTiming);
        cudaEventCreateWithFlags(&e1, cudaEventDisableTiming);
        cudaEventCreateWithFlags(&e2, cudaEventDisableTiming);
        cudaEventCreateWithFlags(&e4, cudaEventDisableTiming);
        cudaEventCreateWithFlags(&eP, cudaEventDisableTiming);
        cudaFuncSetAttribute(tgemm_kernel, cudaFuncAttributeMaxDynamicSharedMemorySize, TG_SMEM);
    }

    float* S = nullptr;
    cudaGetSymbolAddress((void**)&S, g_scratch);
    int* I = nullptr;
    cudaGetSymbolAddress((void**)&I, g_iscratch);

    __half* T1CH = (__half*)(S + OFF_T1C);
    __half* SFCH = (__half*)(S + OFF_SFC);
    __half* T1DH = (__half*)(S + OFF_T1D);
    __half* ZAb = (__half*)(S + OFF_ZA);
    __half* ZCH = (__half*)(S + OFF_ZC);
    __half* EXPSP = (__half*)(S + OFF_EXPSP);
    __half* DAb = (__half*)(S + OFF_DA);
    float* CP  = S + OFF_CP;
    float* DP  = S + OFF_DP;
    __half* XC = (__half*)(S + OFF_XC);
    __half* YC = (__half*)(S + OFF_YC);
    __half* WSCb = (__half*)(S + OFF_WSC);
    __half* WSDb = (__half*)(S + OFF_WSD);
    __half* WCSb = (__half*)(S + OFF_WCS);
    __half* WCCb = (__half*)(S + OFF_WCC);
    __half* WDDb = (__half*)(S + OFF_WDD);
    float* LCV = S + OFF_LCV;   float* LDV = S + OFF_LDV;
    float* DRC = S + OFF_DRC;   float* DCC = S + OFF_DCC;
    float* DRD = S + OFF_DRD;   float* DCD = S + OFF_DCD;
    float* LRSC = S + OFF_LRSC; float* LCSC = S + OFF_LCSC;
    float* LRSD = S + OFF_LRSD; float* LCSD = S + OFF_LCSD;
    float* DXA = S + OFF_DXA;   float* DYA = S + OFF_DYA;
    float* SELFC = S + OFF_SELFC; float* SELFD = S + OFF_SELFD;
    float* RNX = S + OFF_RNX;   float* RNY = S + OFF_RNY;
    float* BSC = S + OFF_BSC;   float* BSD = S + OFF_BSD;

    int* LAPC_IDX = I + I_LAPC_IDX; int* LAPD_IDX = I + I_LAPD_IDX;
    int* ADJC_IDX = I + I_ADJC_IDX; int* ADJD_IDX = I + I_ADJD_IDX;
    int* LAPC_CNT = I + I_LAPC_CNT; int* LAPD_CNT = I + I_LAPD_CNT;
    int* ADJC_CNT = I + I_ADJC_CNT; int* ADJD_CNT = I + I_ADJD_CNT;

    cudaStream_t st = 0;
    const int D = DIMF;

    cudaEventRecord(eF, st);
    cudaStreamWaitEvent(s1, eF, 0);

    // ---- stream 0: extraction chain (R13 serial front) ----
    cudaMemsetAsync(DCC, 0, S_NC * sizeof(float), st);
    cudaMemsetAsync(DCD, 0, S_ND * sizeof(float), st);
    cudaMemsetAsync(ADJD_CNT, 0, S_ND * sizeof(int), st);
    knn_extract_kernel<<<NCELL, 256, NCELL * sizeof(float), st>>>(
        cell_sim, NCELL, LAPC_IDX, LCV, LAPC_CNT, DRC, DCC);
    knn_extract_kernel<<<NDRUG, 256, NDRUG * sizeof(float), st>>>(
        drug_sim, NDRUG, LAPD_IDX, LDV, LAPD_CNT, DRD, DCD);
    extract_adj_kernel<<<NCELL, 256, 0, st>>>(adj, ADJC_IDX, ADJC_CNT, ADJD_IDX, ADJD_CNT);
    prep_scales_kernel<<<(NCELL + 255) / 256, 256, 0, st>>>(
        DRC, DCC, DRD, DCD, ADJC_CNT, ADJD_CNT,
        LRSC, LCSC, LRSD, LCSD, DXA, DYA, SELFC, SELFD);
    split_row_kernel<<<NDRUG, 256, 0, st>>>(figm, SELFD, D, DAb, 3 * D);
    spmm_kernel<<<NCELL, 256, 0, st>>>(LAPC_IDX, LCV, LAPC_CNT, CAP_L, LRSC, LCSC,
                                       expm, D, T1CH, D);
    spmm_kernel<<<NDRUG, 256, 0, st>>>(LAPD_IDX, LDV, LAPD_CNT, CAP_L, LRSD, LCSD,
                                       figm, D, T1DH, D);
    cudaEventRecord(e0, st);

    // ---- stream 1: independent splits ----
    bsum_kernel<<<(D + 255) / 256, 256, 0, s1>>>(b_cs, b_c1, b_c2, b_ds, b_d1, b_d2, BSC, BSD);
    split_row_kernel<<<NCELL, 256, 0, s1>>>(expm, nullptr, D, EXPSP, D);
    split_row_kernel<<<NDRUG, 256, 0, s1>>>(figm, nullptr, D, ZAb, 2 * D);
    split_row_kernel<<<DIMF, 256, 0, s1>>>(W_sc, nullptr, D, WSCb, D);
    split_row_kernel<<<DIMF, 256, 0, s1>>>(W_sd, nullptr, D, WSDb, D);
    split_row_kernel<<<DIMF, 256, 0, s1>>>(W_cs, nullptr, D, WCSb, D);
    split_row_kernel<<<DIMF, 256, 0, s1>>>(W_c1, nullptr, D, WCCb, 2 * D);
    split_row_kernel<<<DIMF, 256, 0, s1>>>(W_c2, nullptr, D, WCCb + D, 2 * D);
    split_row_kernel<<<DIMF, 256, 0, s1>>>(W_ds, nullptr, D, WDDb, 3 * D);
    split_row_kernel<<<DIMF, 256, 0, s1>>>(W_d1, nullptr, D, WDDb + D, 3 * D);
    split_row_kernel<<<DIMF, 256, 0, s1>>>(W_d2, nullptr, D, WDDb + 2 * D, 3 * D);
    cudaEventRecord(eP, s1);

    // ---- stream 1: {sfd gemm -> ZC gemm} ----
    cudaStreamWaitEvent(s1, e0, 0);
    launch_tg(NDRUG, D, D, T1DH, D, WSDb, D,
              (void*)(ZAb + D), 2 * D, 0, 0, 0, 0, F_RELU | F_PACK1, s1);
    launch_tg(NDRUG, D, 2 * D, ZAb, 2 * D, WCCb, 2 * D,
              ZCH, D, 0, 0, 0, 0, F_PACK1, s1);
    cudaEventRecord(e1, s1);

    // ---- stream 0: cell chain ----
    cudaStreamWaitEvent(st, eP, 0);
    launch_tg(NCELL, D, D, T1CH, D, WSCb, D, SFCH, D,
              0, 0, 0, 0, F_RELU | F_PACK1, st);
    spmm_h2_kernel<<<NDRUG, 256, 0, st>>>(ADJD_IDX, ADJD_CNT, CAP_D, DYA, DXA,
                                          EXPSP, SFCH, D,
                                          DAb + D, DAb + 2 * D, 3 * D);
    cudaEventRecord(e2, st);

    launch_tg(NCELL, D, D, EXPSP, D, WCSb, D, CP, D,
              BSC, SELFC, 0, 0, 0, st);
    cudaStreamWaitEvent(st, e1, 0);
    spmm_gate_kernel<<<NCELL, 256, D * sizeof(float), st>>>(
        ADJC_IDX, ADJC_CNT, CAP_C, DXA, DYA, ZCH, D, CP, expm, D, XC, RNX);

    // ---- stream 1: DP chain ----
    cudaStreamWaitEvent(s1, e2, 0);
    launch_tg(NDRUG, D, 3 * D, DAb, 3 * D, WDDb, 3 * D,
              DP, D, BSD, 0, 0, 0, 0, s1);
    gate_center_kernel<<<NDRUG, 256, D * sizeof(float), s1>>>(DP, figm, D, YC, RNY);
    cudaEventRecord(e4, s1);

    // ---- decoder ----
    cudaStreamWaitEvent(st, e4, 0);
    launch_tg(NCELL, NDRUG, D, XC, D, YC, D,
              out, NDRUG, 0, 0, RNX, RNY, F_PEARSON, st);
}